// round 9
// baseline (speedup 1.0000x reference)
#include <cuda_runtime.h>
#include <cuda_fp16.h>

#define S_NODES 8192
#define NN      8384
#define CH      128
#define BB      2
#define EE      262144
#define CAP     96            // bucket capacity per node per CSR type

// ---------------- scratch (device globals; no allocation allowed) -----------
__device__ float  g_h0[BB * NN * CH];
__device__ float  g_h1[BB * NN * CH];
__device__ __half g_hxA[BB * NN * CH];   // fp16 copies of features for gathering
__device__ __half g_hxB[BB * NN * CH];
__device__ float  g_qA[BB * NN];
__device__ float  g_qB[BB * NN];
__device__ float2 g_pdA[BB * NN];        // (p, dinvI) packed per node
__device__ float2 g_pdB[BB * NN];
__device__ float  g_dinvI[BB * NN];      // gcn norm: rsqrt(intra_in_deg + 1)
__device__ float  g_dinvX[BB * NN];      // inter: 1/deg or 0
__device__ int    g_cntI[BB * NN];
__device__ int    g_cntX[BB * NN];
__device__ int    g_bI[BB * NN * CAP];   // intra src buckets
__device__ int    g_bX[BB * NN * CAP];   // inter src buckets

struct alignas(8) h4 { __half2 a, b; };

__device__ __forceinline__ float tanh_fast(float z) {
    float az = fabsf(z);
    float e  = __expf(2.0f * az);
    float r  = 1.0f - 2.0f / (e + 1.0f);
    return copysignf(r, z);
}

// ---------------- bucket build ---------------------------------------------
__global__ void k_zero() {
    int i = blockIdx.x * blockDim.x + threadIdx.x;
    if (i < BB * NN) { g_cntI[i] = 0; g_cntX[i] = 0; }
}

__global__ void k_scatter(const int* __restrict__ ei) {
    int i = blockIdx.x * blockDim.x + threadIdx.x;
    if (i >= BB * EE) return;
    int b = i / EE, e = i - b * EE;
    int s = ei[b * 2 * EE + e];
    int d = ei[b * 2 * EE + EE + e];
    int dn = b * NN + d;
    bool intra = (s < S_NODES) == (d < S_NODES);
    if (intra) {
        int pos = atomicAdd(&g_cntI[dn], 1);
        if (pos < CAP) g_bI[dn * CAP + pos] = s;
    } else {
        int pos = atomicAdd(&g_cntX[dn], 1);
        if (pos < CAP) g_bX[dn * CAP + pos] = s;
    }
}

// ---------------- prep: dinv + initial dots + fp16 copy + bucket sort ------
// warp roles: [0, BB*NN) = dots/dinv; [BB*NN, 3*BB*NN) = sort (intra then inter)
__global__ void k_prep(const float* __restrict__ x,
                       float* __restrict__ qout, float2* __restrict__ pdout,
                       h4* __restrict__ hxout,
                       const float* __restrict__ WaS, const float* __restrict__ WbS,
                       const float* __restrict__ WaT, const float* __restrict__ WbT) {
    int t = blockIdx.x * blockDim.x + threadIdx.x;
    int wg = t >> 5, lane = t & 31;
    if (wg >= 3 * BB * NN) return;

    if (wg < BB * NN) {            // ---- dots + dinv role ----
        int w = wg;
        int v = w % NN;
        int cI = g_cntI[w];
        int cX = g_cntX[w];
        float dI = rsqrtf((float)(cI + 1));
        float dX = (cX > 0) ? (1.0f / (float)cX) : 0.0f;
        if (lane == 0) { g_dinvI[w] = dI; g_dinvX[w] = dX; }
        const float* Wa = (v < S_NODES) ? WaS : WaT;
        const float* Wb = (v < S_NODES) ? WbS : WbT;
        float4 xv = ((const float4*)x)[w * 32 + lane];
        h4 hv;
        hv.a = __floats2half2_rn(xv.x, xv.y);
        hv.b = __floats2half2_rn(xv.z, xv.w);
        hxout[w * 32 + lane] = hv;
        float4 wa = ((const float4*)Wa)[lane];
        float4 wb = ((const float4*)Wb)[lane];
        float qs = xv.x * wa.x + xv.y * wa.y + xv.z * wa.z + xv.w * wa.w;
        float ps = xv.x * wb.x + xv.y * wb.y + xv.z * wb.z + xv.w * wb.w;
        #pragma unroll
        for (int o = 16; o > 0; o >>= 1) {
            qs += __shfl_xor_sync(0xffffffffu, qs, o);
            ps += __shfl_xor_sync(0xffffffffu, ps, o);
        }
        if (lane == 0) { qout[w] = qs; pdout[w] = make_float2(ps, dI); }
    } else {                        // ---- sort role (bitonic, warp per node) ----
        int m = wg - BB * NN;
        bool intra = m < BB * NN;
        int n = intra ? m : m - BB * NN;     // global node index
        int* bucket = (intra ? g_bI : g_bX) + n * CAP;
        int cnt = intra ? g_cntI[n] : g_cntX[n];
        int len = min(cnt, CAP);
        if (len <= 1) return;
        if (len <= 64) {
            int r0 = (lane < len)      ? bucket[lane]      : 0x7fffffff;
            int r1 = (32 + lane < len) ? bucket[32 + lane] : 0x7fffffff;
            for (int k = 2; k <= 64; k <<= 1) {
                for (int j = k >> 1; j > 0; j >>= 1) {
                    if (j == 32) {
                        int lo = min(r0, r1), hi = max(r0, r1);
                        r0 = lo; r1 = hi;
                    } else {
                        int o0 = __shfl_xor_sync(0xffffffffu, r0, j);
                        int o1 = __shfl_xor_sync(0xffffffffu, r1, j);
                        bool bit = (lane & j) != 0;
                        bool up0 = ((lane & k) == 0);
                        bool up1 = (((lane + 32) & k) == 0);
                        r0 = (bit != up0) ? min(r0, o0) : max(r0, o0);
                        r1 = (bit != up1) ? min(r1, o1) : max(r1, o1);
                    }
                }
            }
            if (lane < len)      bucket[lane]      = r0;
            if (32 + lane < len) bucket[32 + lane] = r1;
        } else if (lane == 0) {      // astronomically rare
            for (int i = 1; i < len; i++) {
                int key = bucket[i]; int j = i - 1;
                while (j >= 0 && bucket[j] > key) { bucket[j + 1] = bucket[j]; j--; }
                bucket[j + 1] = key;
            }
        }
    }
}

// ---------------- gather: warp per node, half-warp per edge ----------------
// lanes 0-15 process even edges, 16-31 odd edges; each lane loads 16B (8 ch)
// of the fp16 source row. Residual/self-loop path stays fp32.
template <bool INTRA, bool RELU, bool DOTS, bool WRITEH>
__global__ void k_gather(const float* __restrict__ xin, float* __restrict__ xout,
                         const __half* __restrict__ hxin, h4* __restrict__ hxout,
                         const float* __restrict__ qin, const float2* __restrict__ pdin,
                         float* __restrict__ qout, float2* __restrict__ pdout,
                         const float* __restrict__ WaS, const float* __restrict__ WbS,
                         const float* __restrict__ WaT, const float* __restrict__ WbT) {
    int t = blockIdx.x * blockDim.x + threadIdx.x;
    int w = t >> 5, lane = t & 31;
    if (w >= BB * NN) return;
    int b = w / NN;
    int v = w - b * NN;
    int h = lane >> 4, l16 = lane & 15;
    int bNN = b * NN;

    float qv = qin[w];
    float dv = INTRA ? g_dinvI[w] : g_dinvX[w];

    const int* __restrict__ bucket = (INTRA ? g_bI : g_bX) + w * CAP;
    int len = min(INTRA ? g_cntI[w] : g_cntX[w], CAP);

    const uint4* __restrict__ hx4 = (const uint4*)hxin;   // 16 uint4 per node row

    float a0 = 0.f, a1 = 0.f, a2 = 0.f, a3 = 0.f;
    float a4 = 0.f, a5 = 0.f, a6 = 0.f, a7 = 0.f;

    int nPairs = (len + 1) >> 1;
    for (int i = 0; i < nPairs; i += 2) {
        int e0 = 2 * i + h;
        int e1 = e0 + 2;
        bool v0 = e0 < len;
        bool v1 = (i + 1 < nPairs) && (e1 < len);
        int s0 = v0 ? bucket[e0] : 0;
        int s1 = v1 ? bucket[e1] : 0;
        float2 p0 = pdin[bNN + s0];
        float2 p1 = pdin[bNN + s1];
        uint4 hv0 = hx4[(bNN + s0) * 16 + l16];
        uint4 hv1 = hx4[(bNN + s1) * 16 + l16];
        float c0 = v0 ? tanh_fast(qv + p0.x) * (INTRA ? dv * p0.y : dv) : 0.f;
        float c1 = v1 ? tanh_fast(qv + p1.x) * (INTRA ? dv * p1.y : dv) : 0.f;
        {
            float2 f0 = __half22float2(*(const __half2*)&hv0.x);
            float2 f1 = __half22float2(*(const __half2*)&hv0.y);
            float2 f2 = __half22float2(*(const __half2*)&hv0.z);
            float2 f3 = __half22float2(*(const __half2*)&hv0.w);
            a0 += c0 * f0.x; a1 += c0 * f0.y; a2 += c0 * f1.x; a3 += c0 * f1.y;
            a4 += c0 * f2.x; a5 += c0 * f2.y; a6 += c0 * f3.x; a7 += c0 * f3.y;
        }
        {
            float2 f0 = __half22float2(*(const __half2*)&hv1.x);
            float2 f1 = __half22float2(*(const __half2*)&hv1.y);
            float2 f2 = __half22float2(*(const __half2*)&hv1.z);
            float2 f3 = __half22float2(*(const __half2*)&hv1.w);
            a0 += c1 * f0.x; a1 += c1 * f0.y; a2 += c1 * f1.x; a3 += c1 * f1.y;
            a4 += c1 * f2.x; a5 += c1 * f2.y; a6 += c1 * f3.x; a7 += c1 * f3.y;
        }
    }

    // combine even/odd halves: every lane ends with the full sum for its 8 ch
    #pragma unroll
    for (int o = 16; o >= 16; o >>= 1) {  // single xor-16 step
        a0 += __shfl_xor_sync(0xffffffffu, a0, 16);
        a1 += __shfl_xor_sync(0xffffffffu, a1, 16);
        a2 += __shfl_xor_sync(0xffffffffu, a2, 16);
        a3 += __shfl_xor_sync(0xffffffffu, a3, 16);
        a4 += __shfl_xor_sync(0xffffffffu, a4, 16);
        a5 += __shfl_xor_sync(0xffffffffu, a5, 16);
        a6 += __shfl_xor_sync(0xffffffffu, a6, 16);
        a7 += __shfl_xor_sync(0xffffffffu, a7, 16);
    }

    // redistribute 8-ch-per-16-lane -> 4-ch-per-32-lane (float4 epilogue)
    int srcl = lane >> 1;
    float b0 = __shfl_sync(0xffffffffu, a0, srcl);
    float b1 = __shfl_sync(0xffffffffu, a1, srcl);
    float b2 = __shfl_sync(0xffffffffu, a2, srcl);
    float b3 = __shfl_sync(0xffffffffu, a3, srcl);
    float b4 = __shfl_sync(0xffffffffu, a4, srcl);
    float b5 = __shfl_sync(0xffffffffu, a5, srcl);
    float b6 = __shfl_sync(0xffffffffu, a6, srcl);
    float b7 = __shfl_sync(0xffffffffu, a7, srcl);
    bool hi = (lane & 1) != 0;
    float4 acc;
    acc.x = hi ? b4 : b0;
    acc.y = hi ? b5 : b1;
    acc.z = hi ? b6 : b2;
    acc.w = hi ? b7 : b3;

    float4 xv = ((const float4*)xin)[w * 32 + lane];
    if (INTRA) {  // self loop in fp32: alpha_self = tanh(q+p), norm = dinv^2
        float cs = tanh_fast(qv + pdin[w].x) * dv * dv;
        acc.x += cs * xv.x; acc.y += cs * xv.y;
        acc.z += cs * xv.z; acc.w += cs * xv.w;
    }
    float4 o;
    o.x = xv.x + acc.x; o.y = xv.y + acc.y;
    o.z = xv.z + acc.z; o.w = xv.w + acc.w;
    if (RELU) {
        o.x = fmaxf(o.x, 0.f); o.y = fmaxf(o.y, 0.f);
        o.z = fmaxf(o.z, 0.f); o.w = fmaxf(o.w, 0.f);
    }
    ((float4*)xout)[w * 32 + lane] = o;
    if (WRITEH) {
        h4 ho;
        ho.a = __floats2half2_rn(o.x, o.y);
        ho.b = __floats2half2_rn(o.z, o.w);
        hxout[w * 32 + lane] = ho;
    }

    if (DOTS) {  // q,p for the NEXT pass from the freshly computed output
        const float* Wa = (v < S_NODES) ? WaS : WaT;
        const float* Wb = (v < S_NODES) ? WbS : WbT;
        float4 wa = ((const float4*)Wa)[lane];
        float4 wb = ((const float4*)Wb)[lane];
        float qs = o.x * wa.x + o.y * wa.y + o.z * wa.z + o.w * wa.w;
        float ps = o.x * wb.x + o.y * wb.y + o.z * wb.z + o.w * wb.w;
        #pragma unroll
        for (int off = 16; off > 0; off >>= 1) {
            qs += __shfl_xor_sync(0xffffffffu, qs, off);
            ps += __shfl_xor_sync(0xffffffffu, ps, off);
        }
        if (lane == 0) { qout[w] = qs; pdout[w] = make_float2(ps, g_dinvI[w]); }
    }
}

// ---------------- launch ---------------------------------------------------
extern "C" void kernel_launch(void* const* d_in, const int* in_sizes, int n_in,
                              void* d_out, int out_size) {
    const float* x   = (const float*)d_in[0];
    const int*   ei  = (const int*)d_in[1];
    const float* Wss = (const float*)d_in[2];
    const float* Wtt = (const float*)d_in[3];
    const float* Wst = (const float*)d_in[4];
    const float* Wts = (const float*)d_in[5];
    float* out = (float*)d_out;

    float *h0, *h1, *qA, *qB;
    float2 *pdA, *pdB;
    h4 *hxA, *hxB;
    __half *hxAp, *hxBp;
    cudaGetSymbolAddress((void**)&h0,   g_h0);
    cudaGetSymbolAddress((void**)&h1,   g_h1);
    cudaGetSymbolAddress((void**)&qA,   g_qA);
    cudaGetSymbolAddress((void**)&qB,   g_qB);
    cudaGetSymbolAddress((void**)&pdA,  g_pdA);
    cudaGetSymbolAddress((void**)&pdB,  g_pdB);
    cudaGetSymbolAddress((void**)&hxAp, g_hxA);
    cudaGetSymbolAddress((void**)&hxBp, g_hxB);
    hxA = (h4*)hxAp; hxB = (h4*)hxBp;

    // bucket CSR build (depends only on edge_index; recomputed every call)
    k_zero<<<(BB * NN + 255) / 256, 256>>>();
    k_scatter<<<(BB * EE + 255) / 256, 256>>>(ei);

    // prep: dinv + initial dots (intra L0 weights) + fp16 copy + bucket sort
    k_prep<<<(3 * BB * NN * 32 + 255) / 256, 256>>>(
        x, qA, pdA, hxA, Wss, Wss + 128, Wtt, Wtt + 128);

    int ng = (BB * NN * 32 + 255) / 256;   // warp-per-node grids

    // pass 0: intra L0, relu; fused dots for pass 1 (inter L0) -> set B, hxB
    k_gather<true, true, true, true><<<ng, 256>>>(
        x, h0, hxAp, hxB, qA, pdA, qB, pdB,
        Wts, Wst + 128, Wst, Wts + 128);

    // pass 1: inter L0, relu; fused dots for pass 2 (intra L1) -> set A, hxA
    k_gather<false, true, true, true><<<ng, 256>>>(
        h0, h1, hxBp, hxA, qB, pdB, qA, pdA,
        Wss + 256, Wss + 384, Wtt + 256, Wtt + 384);

    // pass 2: intra L1, relu; fused dots for pass 3 (inter L1) -> set B, hxB
    k_gather<true, true, true, true><<<ng, 256>>>(
        h1, h0, hxAp, hxB, qA, pdA, qB, pdB,
        Wts + 256, Wst + 384, Wst + 256, Wts + 384);

    // pass 3: inter L1, no relu, write straight to d_out
    k_gather<false, false, false, false><<<ng, 256>>>(
        h0, out, hxBp, nullptr, qB, pdB, nullptr, nullptr,
        nullptr, nullptr, nullptr, nullptr);
}

// round 10
// speedup vs baseline: 1.2374x; 1.2374x over previous
#include <cuda_runtime.h>

#define S_NODES 8192
#define NN      8384
#define CH      128
#define BB      2
#define EE      262144
#define CAP     96            // bucket capacity per node per CSR type

// ---------------- scratch (device globals; no allocation allowed) -----------
__device__ float  g_h0[BB * NN * CH];
__device__ float  g_h1[BB * NN * CH];
__device__ float  g_qA[BB * NN];
__device__ float  g_qB[BB * NN];
__device__ float2 g_pdA[BB * NN];        // (p, dinvI) packed per node
__device__ float2 g_pdB[BB * NN];
__device__ float  g_dinvI[BB * NN];      // gcn norm: rsqrt(intra_in_deg + 1)
__device__ float  g_dinvX[BB * NN];      // inter: 1/deg or 0
__device__ int    g_cntI[BB * NN];
__device__ int    g_cntX[BB * NN];
__device__ int    g_bI[BB * NN * CAP];   // intra src buckets
__device__ int    g_bX[BB * NN * CAP];   // inter src buckets
__device__ int2   g_scI[BB * NN * CAP];  // packed (src, coef) per slot
__device__ int2   g_scX[BB * NN * CAP];

__device__ __forceinline__ float tanh_fast(float z) {
    float az = fabsf(z);
    float e  = __expf(2.0f * az);
    float r  = 1.0f - 2.0f / (e + 1.0f);
    return copysignf(r, z);
}

// packed f32x2 helpers (sm_103a; ptxas emits FFMA2 only via PTX f32x2)
__device__ __forceinline__ unsigned long long pack_dup(float c) {
    unsigned long long r;
    unsigned int cb = __float_as_uint(c);
    asm("mov.b64 %0, {%1, %1};" : "=l"(r) : "r"(cb));
    return r;
}
__device__ __forceinline__ void fma_x2(unsigned long long& d,
                                       unsigned long long a,
                                       unsigned long long b) {
    asm("fma.rn.f32x2 %0, %1, %2, %0;" : "+l"(d) : "l"(a), "l"(b));
}
__device__ __forceinline__ float2 unpack_x2(unsigned long long v) {
    unsigned int lo, hi;
    asm("mov.b64 {%0, %1}, %2;" : "=r"(lo), "=r"(hi) : "l"(v));
    return make_float2(__uint_as_float(lo), __uint_as_float(hi));
}

// ---------------- bucket build ---------------------------------------------
__global__ void k_zero() {
    int i = blockIdx.x * blockDim.x + threadIdx.x;
    if (i < BB * NN) { g_cntI[i] = 0; g_cntX[i] = 0; }
}

__global__ void k_scatter(const int* __restrict__ ei) {
    int i = blockIdx.x * blockDim.x + threadIdx.x;
    if (i >= BB * EE) return;
    int b = i / EE, e = i - b * EE;
    int s = ei[b * 2 * EE + e];
    int d = ei[b * 2 * EE + EE + e];
    int dn = b * NN + d;
    bool intra = (s < S_NODES) == (d < S_NODES);
    if (intra) {
        int pos = atomicAdd(&g_cntI[dn], 1);
        if (pos < CAP) g_bI[dn * CAP + pos] = s;
    } else {
        int pos = atomicAdd(&g_cntX[dn], 1);
        if (pos < CAP) g_bX[dn * CAP + pos] = s;
    }
}

// ---------------- prep: dinv + initial dots + bucket sort ------------------
// warp roles: [0, BB*NN) = dots/dinv; [BB*NN, 3*BB*NN) = sort (intra then inter)
__global__ void k_prep(const float* __restrict__ x,
                       float* __restrict__ qout, float2* __restrict__ pdout,
                       const float* __restrict__ WaS, const float* __restrict__ WbS,
                       const float* __restrict__ WaT, const float* __restrict__ WbT) {
    int t = blockIdx.x * blockDim.x + threadIdx.x;
    int wg = t >> 5, lane = t & 31;
    if (wg >= 3 * BB * NN) return;

    if (wg < BB * NN) {            // ---- dots + dinv role ----
        int w = wg;
        int v = w % NN;
        int cI = g_cntI[w];
        int cX = g_cntX[w];
        float dI = rsqrtf((float)(cI + 1));
        float dX = (cX > 0) ? (1.0f / (float)cX) : 0.0f;
        if (lane == 0) { g_dinvI[w] = dI; g_dinvX[w] = dX; }
        const float* Wa = (v < S_NODES) ? WaS : WaT;
        const float* Wb = (v < S_NODES) ? WbS : WbT;
        float4 xv = ((const float4*)x)[w * 32 + lane];
        float4 wa = ((const float4*)Wa)[lane];
        float4 wb = ((const float4*)Wb)[lane];
        float qs = xv.x * wa.x + xv.y * wa.y + xv.z * wa.z + xv.w * wa.w;
        float ps = xv.x * wb.x + xv.y * wb.y + xv.z * wb.z + xv.w * wb.w;
        #pragma unroll
        for (int o = 16; o > 0; o >>= 1) {
            qs += __shfl_xor_sync(0xffffffffu, qs, o);
            ps += __shfl_xor_sync(0xffffffffu, ps, o);
        }
        if (lane == 0) { qout[w] = qs; pdout[w] = make_float2(ps, dI); }
    } else {                        // ---- sort role (bitonic, warp per node) ----
        int m = wg - BB * NN;
        bool intra = m < BB * NN;
        int n = intra ? m : m - BB * NN;     // global node index
        int* bucket = (intra ? g_bI : g_bX) + n * CAP;
        int cnt = intra ? g_cntI[n] : g_cntX[n];
        int len = min(cnt, CAP);
        if (len <= 1) return;
        if (len <= 64) {
            int r0 = (lane < len)      ? bucket[lane]      : 0x7fffffff;
            int r1 = (32 + lane < len) ? bucket[32 + lane] : 0x7fffffff;
            for (int k = 2; k <= 64; k <<= 1) {
                for (int j = k >> 1; j > 0; j >>= 1) {
                    if (j == 32) {
                        int lo = min(r0, r1), hi = max(r0, r1);
                        r0 = lo; r1 = hi;
                    } else {
                        int o0 = __shfl_xor_sync(0xffffffffu, r0, j);
                        int o1 = __shfl_xor_sync(0xffffffffu, r1, j);
                        bool bit = (lane & j) != 0;
                        bool up0 = ((lane & k) == 0);
                        bool up1 = (((lane + 32) & k) == 0);
                        r0 = (bit != up0) ? min(r0, o0) : max(r0, o0);
                        r1 = (bit != up1) ? min(r1, o1) : max(r1, o1);
                    }
                }
            }
            if (lane < len)      bucket[lane]      = r0;
            if (32 + lane < len) bucket[32 + lane] = r1;
        } else if (lane == 0) {      // astronomically rare
            for (int i = 1; i < len; i++) {
                int key = bucket[i]; int j = i - 1;
                while (j >= 0 && bucket[j] > key) { bucket[j + 1] = bucket[j]; j--; }
                bucket[j + 1] = key;
            }
        }
    }
}

// ---------------- edge-parallel coefficients into bucket slots -------------
// coef = tanh(q[dst] + p[src]) * norm, packed (src, coef) for the gather.
template <bool INTRA>
__global__ void k_coef(const float* __restrict__ q, const float2* __restrict__ pd) {
    int i = blockIdx.x * blockDim.x + threadIdx.x;
    if (i >= BB * NN * CAP) return;
    int node = i / CAP;                 // global dst node
    int pos  = i - node * CAP;
    int cnt = min(INTRA ? g_cntI[node] : g_cntX[node], CAP);
    if (pos >= cnt) return;
    int s = (INTRA ? g_bI : g_bX)[i];
    int b = node / NN;
    int sn = b * NN + s;
    float2 ps = pd[sn];
    float z = tanh_fast(q[node] + ps.x);
    float c = INTRA ? z * g_dinvI[node] * ps.y : z * g_dinvX[node];
    (INTRA ? g_scI : g_scX)[i] = make_int2(s, __float_as_int(c));
}

// ---------------- gather: warp per node, f32x2 packed FMA ------------------
template <bool INTRA, bool RELU, bool DOTS>
__global__ void k_gather(const float* __restrict__ xin, float* __restrict__ xout,
                         const float* __restrict__ qin, const float2* __restrict__ pdin,
                         float* __restrict__ qout, float2* __restrict__ pdout,
                         const float* __restrict__ WaS, const float* __restrict__ WbS,
                         const float* __restrict__ WaT, const float* __restrict__ WbT) {
    int t = blockIdx.x * blockDim.x + threadIdx.x;
    int w = t >> 5, lane = t & 31;
    if (w >= BB * NN) return;
    int b = w / NN;
    int v = w - b * NN;
    int bNN = b * NN;

    int len = min(INTRA ? g_cntI[w] : g_cntX[w], CAP);
    const int2* __restrict__ sc = (INTRA ? g_scI : g_scX) + w * CAP;
    const ulonglong2* __restrict__ x2 = (const ulonglong2*)xin;  // 16B per lane

    unsigned long long acc01 = 0, acc23 = 0;  // packed (0f,0f)

    int e = 0;
    for (; e + 4 <= len; e += 4) {
        int2 s0 = sc[e], s1 = sc[e + 1], s2 = sc[e + 2], s3 = sc[e + 3];
        ulonglong2 x0 = x2[(bNN + s0.x) * 32 + lane];
        ulonglong2 x1 = x2[(bNN + s1.x) * 32 + lane];
        ulonglong2 xx2 = x2[(bNN + s2.x) * 32 + lane];
        ulonglong2 x3 = x2[(bNN + s3.x) * 32 + lane];
        unsigned long long c0 = pack_dup(__int_as_float(s0.y));
        unsigned long long c1 = pack_dup(__int_as_float(s1.y));
        unsigned long long c2 = pack_dup(__int_as_float(s2.y));
        unsigned long long c3 = pack_dup(__int_as_float(s3.y));
        fma_x2(acc01, c0, x0.x); fma_x2(acc23, c0, x0.y);
        fma_x2(acc01, c1, x1.x); fma_x2(acc23, c1, x1.y);
        fma_x2(acc01, c2, xx2.x); fma_x2(acc23, c2, xx2.y);
        fma_x2(acc01, c3, x3.x); fma_x2(acc23, c3, x3.y);
    }
    for (; e < len; e++) {
        int2 se = sc[e];
        ulonglong2 xe = x2[(bNN + se.x) * 32 + lane];
        unsigned long long ce = pack_dup(__int_as_float(se.y));
        fma_x2(acc01, ce, xe.x); fma_x2(acc23, ce, xe.y);
    }

    float2 a01 = unpack_x2(acc01);
    float2 a23 = unpack_x2(acc23);
    float4 acc = make_float4(a01.x, a01.y, a23.x, a23.y);

    float4 xv = ((const float4*)xin)[w * 32 + lane];
    float qv = qin[w];
    float dv = INTRA ? g_dinvI[w] : g_dinvX[w];
    if (INTRA) {  // self loop: alpha_self = tanh(q+p), norm = 1/deg = dinv^2
        float cs = tanh_fast(qv + pdin[w].x) * dv * dv;
        acc.x += cs * xv.x; acc.y += cs * xv.y;
        acc.z += cs * xv.z; acc.w += cs * xv.w;
    }
    float4 o;
    o.x = xv.x + acc.x; o.y = xv.y + acc.y;
    o.z = xv.z + acc.z; o.w = xv.w + acc.w;
    if (RELU) {
        o.x = fmaxf(o.x, 0.f); o.y = fmaxf(o.y, 0.f);
        o.z = fmaxf(o.z, 0.f); o.w = fmaxf(o.w, 0.f);
    }
    ((float4*)xout)[w * 32 + lane] = o;

    if (DOTS) {  // q,p for the NEXT pass from the freshly computed output
        const float* Wa = (v < S_NODES) ? WaS : WaT;
        const float* Wb = (v < S_NODES) ? WbS : WbT;
        float4 wa = ((const float4*)Wa)[lane];
        float4 wb = ((const float4*)Wb)[lane];
        float qs = o.x * wa.x + o.y * wa.y + o.z * wa.z + o.w * wa.w;
        float ps = o.x * wb.x + o.y * wb.y + o.z * wb.z + o.w * wb.w;
        #pragma unroll
        for (int off = 16; off > 0; off >>= 1) {
            qs += __shfl_xor_sync(0xffffffffu, qs, off);
            ps += __shfl_xor_sync(0xffffffffu, ps, off);
        }
        if (lane == 0) { qout[w] = qs; pdout[w] = make_float2(ps, g_dinvI[w]); }
    }
}

// ---------------- launch ---------------------------------------------------
extern "C" void kernel_launch(void* const* d_in, const int* in_sizes, int n_in,
                              void* d_out, int out_size) {
    const float* x   = (const float*)d_in[0];
    const int*   ei  = (const int*)d_in[1];
    const float* Wss = (const float*)d_in[2];
    const float* Wtt = (const float*)d_in[3];
    const float* Wst = (const float*)d_in[4];
    const float* Wts = (const float*)d_in[5];
    float* out = (float*)d_out;

    float *h0, *h1, *qA, *qB;
    float2 *pdA, *pdB;
    cudaGetSymbolAddress((void**)&h0,  g_h0);
    cudaGetSymbolAddress((void**)&h1,  g_h1);
    cudaGetSymbolAddress((void**)&qA,  g_qA);
    cudaGetSymbolAddress((void**)&qB,  g_qB);
    cudaGetSymbolAddress((void**)&pdA, g_pdA);
    cudaGetSymbolAddress((void**)&pdB, g_pdB);

    // bucket CSR build (depends only on edge_index; recomputed every call)
    k_zero<<<(BB * NN + 255) / 256, 256>>>();
    k_scatter<<<(BB * EE + 255) / 256, 256>>>(ei);

    // prep: dinv + initial dots (intra L0 weights) + bucket sort
    k_prep<<<(3 * BB * NN * 32 + 255) / 256, 256>>>(
        x, qA, pdA, Wss, Wss + 128, Wtt, Wtt + 128);

    int ng = (BB * NN * 32 + 255) / 256;     // warp-per-node grids
    int nc = (BB * NN * CAP + 255) / 256;    // slot-parallel grids

    // pass 0: intra L0, relu; fused dots for pass 1 (inter L0) -> set B
    k_coef<true><<<nc, 256>>>(qA, pdA);
    k_gather<true, true, true><<<ng, 256>>>(
        x, h0, qA, pdA, qB, pdB, Wts, Wst + 128, Wst, Wts + 128);

    // pass 1: inter L0, relu; fused dots for pass 2 (intra L1) -> set A
    k_coef<false><<<nc, 256>>>(qB, pdB);
    k_gather<false, true, true><<<ng, 256>>>(
        h0, h1, qB, pdB, qA, pdA, Wss + 256, Wss + 384, Wtt + 256, Wtt + 384);

    // pass 2: intra L1, relu; fused dots for pass 3 (inter L1) -> set B
    k_coef<true><<<nc, 256>>>(qA, pdA);
    k_gather<true, true, true><<<ng, 256>>>(
        h1, h0, qA, pdA, qB, pdB, Wts + 256, Wst + 384, Wst + 256, Wts + 384);

    // pass 3: inter L1, no relu, write straight to d_out
    k_coef<false><<<nc, 256>>>(qB, pdB);
    k_gather<false, false, false><<<ng, 256>>>(
        h0, out, qB, pdB, nullptr, nullptr, nullptr, nullptr, nullptr, nullptr);
}

// round 11
// speedup vs baseline: 1.5618x; 1.2622x over previous
#include <cuda_runtime.h>

#define S_NODES 8192
#define NN      8384
#define CH      128
#define BB      2
#define EE      262144
#define CAP     96            // bucket capacity per node per CSR type

// ---------------- scratch (device globals; no allocation allowed) -----------
__device__ float  g_h0[BB * NN * CH];
__device__ float  g_h1[BB * NN * CH];
__device__ float  g_qA[BB * NN];
__device__ float  g_qB[BB * NN];
__device__ float2 g_pdA[BB * NN];        // (p, dinvI) packed per node
__device__ float2 g_pdB[BB * NN];
__device__ float  g_dinvI[BB * NN];      // gcn norm: rsqrt(intra_in_deg + 1)
__device__ float  g_dinvX[BB * NN];      // inter: 1/deg or 0
__device__ int    g_cntI[BB * NN];
__device__ int    g_cntX[BB * NN];
__device__ int    g_bI[BB * NN * CAP];   // intra src buckets
__device__ int    g_bX[BB * NN * CAP];   // inter src buckets

__device__ __forceinline__ float tanh_fast(float z) {
    float az = fabsf(z);
    float e  = __expf(2.0f * az);
    float r  = 1.0f - 2.0f / (e + 1.0f);
    return copysignf(r, z);
}

// packed f32x2 helpers (sm_103a; ptxas emits FFMA2 only via PTX f32x2)
__device__ __forceinline__ unsigned long long pack_dup(float c) {
    unsigned long long r;
    unsigned int cb = __float_as_uint(c);
    asm("mov.b64 %0, {%1, %1};" : "=l"(r) : "r"(cb));
    return r;
}
__device__ __forceinline__ void fma_x2(unsigned long long& d,
                                       unsigned long long a,
                                       unsigned long long b) {
    asm("fma.rn.f32x2 %0, %1, %2, %0;" : "+l"(d) : "l"(a), "l"(b));
}
__device__ __forceinline__ float2 unpack_x2(unsigned long long v) {
    unsigned int lo, hi;
    asm("mov.b64 {%0, %1}, %2;" : "=r"(lo), "=r"(hi) : "l"(v));
    return make_float2(__uint_as_float(lo), __uint_as_float(hi));
}

// ---------------- bucket build ---------------------------------------------
__global__ void k_zero() {
    int i = blockIdx.x * blockDim.x + threadIdx.x;
    if (i < BB * NN) { g_cntI[i] = 0; g_cntX[i] = 0; }
}

__global__ void k_scatter(const int* __restrict__ ei) {
    int i = blockIdx.x * blockDim.x + threadIdx.x;
    if (i >= BB * EE) return;
    int b = i / EE, e = i - b * EE;
    int s = ei[b * 2 * EE + e];
    int d = ei[b * 2 * EE + EE + e];
    int dn = b * NN + d;
    bool intra = (s < S_NODES) == (d < S_NODES);
    if (intra) {
        int pos = atomicAdd(&g_cntI[dn], 1);
        if (pos < CAP) g_bI[dn * CAP + pos] = s;
    } else {
        int pos = atomicAdd(&g_cntX[dn], 1);
        if (pos < CAP) g_bX[dn * CAP + pos] = s;
    }
}

// ---------------- prep: dinv + initial dots + bucket sort ------------------
// warp roles: [0, BB*NN) = dots/dinv; [BB*NN, 3*BB*NN) = sort (intra then inter)
__global__ void k_prep(const float* __restrict__ x,
                       float* __restrict__ qout, float2* __restrict__ pdout,
                       const float* __restrict__ WaS, const float* __restrict__ WbS,
                       const float* __restrict__ WaT, const float* __restrict__ WbT) {
    int t = blockIdx.x * blockDim.x + threadIdx.x;
    int wg = t >> 5, lane = t & 31;
    if (wg >= 3 * BB * NN) return;

    if (wg < BB * NN) {            // ---- dots + dinv role ----
        int w = wg;
        int v = w % NN;
        int cI = g_cntI[w];
        int cX = g_cntX[w];
        float dI = rsqrtf((float)(cI + 1));
        float dX = (cX > 0) ? (1.0f / (float)cX) : 0.0f;
        if (lane == 0) { g_dinvI[w] = dI; g_dinvX[w] = dX; }
        const float* Wa = (v < S_NODES) ? WaS : WaT;
        const float* Wb = (v < S_NODES) ? WbS : WbT;
        float4 xv = ((const float4*)x)[w * 32 + lane];
        float4 wa = ((const float4*)Wa)[lane];
        float4 wb = ((const float4*)Wb)[lane];
        float qs = xv.x * wa.x + xv.y * wa.y + xv.z * wa.z + xv.w * wa.w;
        float ps = xv.x * wb.x + xv.y * wb.y + xv.z * wb.z + xv.w * wb.w;
        #pragma unroll
        for (int o = 16; o > 0; o >>= 1) {
            qs += __shfl_xor_sync(0xffffffffu, qs, o);
            ps += __shfl_xor_sync(0xffffffffu, ps, o);
        }
        if (lane == 0) { qout[w] = qs; pdout[w] = make_float2(ps, dI); }
    } else {                        // ---- sort role (bitonic, warp per node) ----
        int m = wg - BB * NN;
        bool intra = m < BB * NN;
        int n = intra ? m : m - BB * NN;     // global node index
        int* bucket = (intra ? g_bI : g_bX) + n * CAP;
        int cnt = intra ? g_cntI[n] : g_cntX[n];
        int len = min(cnt, CAP);
        if (len <= 1) return;
        if (len <= 64) {
            int r0 = (lane < len)      ? bucket[lane]      : 0x7fffffff;
            int r1 = (32 + lane < len) ? bucket[32 + lane] : 0x7fffffff;
            for (int k = 2; k <= 64; k <<= 1) {
                for (int j = k >> 1; j > 0; j >>= 1) {
                    if (j == 32) {
                        int lo = min(r0, r1), hi = max(r0, r1);
                        r0 = lo; r1 = hi;
                    } else {
                        int o0 = __shfl_xor_sync(0xffffffffu, r0, j);
                        int o1 = __shfl_xor_sync(0xffffffffu, r1, j);
                        bool bit = (lane & j) != 0;
                        bool up0 = ((lane & k) == 0);
                        bool up1 = (((lane + 32) & k) == 0);
                        r0 = (bit != up0) ? min(r0, o0) : max(r0, o0);
                        r1 = (bit != up1) ? min(r1, o1) : max(r1, o1);
                    }
                }
            }
            if (lane < len)      bucket[lane]      = r0;
            if (32 + lane < len) bucket[32 + lane] = r1;
        } else if (lane == 0) {      // astronomically rare
            for (int i = 1; i < len; i++) {
                int key = bucket[i]; int j = i - 1;
                while (j >= 0 && bucket[j] > key) { bucket[j + 1] = bucket[j]; j--; }
                bucket[j + 1] = key;
            }
        }
    }
}

// ---------------- gather: warp per node ------------------------------------
// Phase 1 (lane-parallel): compute (src, coef) for all edges into smem.
// Phase 2 (serial, fixed order): f32x2 packed-FMA accumulate over smem slots.
template <bool INTRA, bool RELU, bool DOTS>
__global__ void k_gather(const float* __restrict__ xin, float* __restrict__ xout,
                         const float* __restrict__ qin, const float2* __restrict__ pdin,
                         float* __restrict__ qout, float2* __restrict__ pdout,
                         const float* __restrict__ WaS, const float* __restrict__ WbS,
                         const float* __restrict__ WaT, const float* __restrict__ WbT) {
    __shared__ int2 s_sc[8][CAP];          // 8 warps/block * 96 slots * 8B = 6KB
    int t = blockIdx.x * blockDim.x + threadIdx.x;
    int w = t >> 5, lane = t & 31;
    if (w >= BB * NN) return;
    int wl = threadIdx.x >> 5;
    int b = w / NN;
    int v = w - b * NN;
    int bNN = b * NN;

    float qv = qin[w];
    float dv = INTRA ? g_dinvI[w] : g_dinvX[w];
    int len = min(INTRA ? g_cntI[w] : g_cntX[w], CAP);
    const int* __restrict__ bucket = (INTRA ? g_bI : g_bX) + w * CAP;

    // phase 1: lane-parallel coefficients into smem
    for (int pos = lane; pos < len; pos += 32) {
        int s = bucket[pos];
        float2 ps = pdin[bNN + s];
        float z = tanh_fast(qv + ps.x);
        float c = INTRA ? z * dv * ps.y : z * dv;
        s_sc[wl][pos] = make_int2(s, __float_as_int(c));
    }
    __syncwarp();

    // phase 2: serial accumulate (fixed sorted order -> deterministic)
    const ulonglong2* __restrict__ x2 = (const ulonglong2*)xin;  // 16B per lane
    unsigned long long acc01 = 0, acc23 = 0;

    int e = 0;
    for (; e + 4 <= len; e += 4) {
        int2 s0 = s_sc[wl][e],     s1 = s_sc[wl][e + 1];
        int2 s2 = s_sc[wl][e + 2], s3 = s_sc[wl][e + 3];
        ulonglong2 x0 = x2[(bNN + s0.x) * 32 + lane];
        ulonglong2 x1 = x2[(bNN + s1.x) * 32 + lane];
        ulonglong2 xx2 = x2[(bNN + s2.x) * 32 + lane];
        ulonglong2 x3 = x2[(bNN + s3.x) * 32 + lane];
        unsigned long long c0 = pack_dup(__int_as_float(s0.y));
        unsigned long long c1 = pack_dup(__int_as_float(s1.y));
        unsigned long long c2 = pack_dup(__int_as_float(s2.y));
        unsigned long long c3 = pack_dup(__int_as_float(s3.y));
        fma_x2(acc01, c0, x0.x);  fma_x2(acc23, c0, x0.y);
        fma_x2(acc01, c1, x1.x);  fma_x2(acc23, c1, x1.y);
        fma_x2(acc01, c2, xx2.x); fma_x2(acc23, c2, xx2.y);
        fma_x2(acc01, c3, x3.x);  fma_x2(acc23, c3, x3.y);
    }
    for (; e < len; e++) {
        int2 se = s_sc[wl][e];
        ulonglong2 xe = x2[(bNN + se.x) * 32 + lane];
        unsigned long long ce = pack_dup(__int_as_float(se.y));
        fma_x2(acc01, ce, xe.x); fma_x2(acc23, ce, xe.y);
    }

    float2 a01 = unpack_x2(acc01);
    float2 a23 = unpack_x2(acc23);
    float4 acc = make_float4(a01.x, a01.y, a23.x, a23.y);

    float4 xv = ((const float4*)xin)[w * 32 + lane];
    if (INTRA) {  // self loop: alpha_self = tanh(q+p), norm = 1/deg = dinv^2
        float cs = tanh_fast(qv + pdin[w].x) * dv * dv;
        acc.x += cs * xv.x; acc.y += cs * xv.y;
        acc.z += cs * xv.z; acc.w += cs * xv.w;
    }
    float4 o;
    o.x = xv.x + acc.x; o.y = xv.y + acc.y;
    o.z = xv.z + acc.z; o.w = xv.w + acc.w;
    if (RELU) {
        o.x = fmaxf(o.x, 0.f); o.y = fmaxf(o.y, 0.f);
        o.z = fmaxf(o.z, 0.f); o.w = fmaxf(o.w, 0.f);
    }
    ((float4*)xout)[w * 32 + lane] = o;

    if (DOTS) {  // q,p for the NEXT pass from the freshly computed output
        const float* Wa = (v < S_NODES) ? WaS : WaT;
        const float* Wb = (v < S_NODES) ? WbS : WbT;
        float4 wa = ((const float4*)Wa)[lane];
        float4 wb = ((const float4*)Wb)[lane];
        float qs = o.x * wa.x + o.y * wa.y + o.z * wa.z + o.w * wa.w;
        float ps = o.x * wb.x + o.y * wb.y + o.z * wb.z + o.w * wb.w;
        #pragma unroll
        for (int off = 16; off > 0; off >>= 1) {
            qs += __shfl_xor_sync(0xffffffffu, qs, off);
            ps += __shfl_xor_sync(0xffffffffu, ps, off);
        }
        if (lane == 0) { qout[w] = qs; pdout[w] = make_float2(ps, g_dinvI[w]); }
    }
}

// ---------------- launch ---------------------------------------------------
extern "C" void kernel_launch(void* const* d_in, const int* in_sizes, int n_in,
                              void* d_out, int out_size) {
    const float* x   = (const float*)d_in[0];
    const int*   ei  = (const int*)d_in[1];
    const float* Wss = (const float*)d_in[2];
    const float* Wtt = (const float*)d_in[3];
    const float* Wst = (const float*)d_in[4];
    const float* Wts = (const float*)d_in[5];
    float* out = (float*)d_out;

    float *h0, *h1, *qA, *qB;
    float2 *pdA, *pdB;
    cudaGetSymbolAddress((void**)&h0,  g_h0);
    cudaGetSymbolAddress((void**)&h1,  g_h1);
    cudaGetSymbolAddress((void**)&qA,  g_qA);
    cudaGetSymbolAddress((void**)&qB,  g_qB);
    cudaGetSymbolAddress((void**)&pdA, g_pdA);
    cudaGetSymbolAddress((void**)&pdB, g_pdB);

    // bucket CSR build (depends only on edge_index; recomputed every call)
    k_zero<<<(BB * NN + 255) / 256, 256>>>();
    k_scatter<<<(BB * EE + 255) / 256, 256>>>(ei);

    // prep: dinv + initial dots (intra L0 weights) + bucket sort
    k_prep<<<(3 * BB * NN * 32 + 255) / 256, 256>>>(
        x, qA, pdA, Wss, Wss + 128, Wtt, Wtt + 128);

    int ng = (BB * NN * 32 + 255) / 256;     // warp-per-node grids

    // pass 0: intra L0, relu; fused dots for pass 1 (inter L0) -> set B
    k_gather<true, true, true><<<ng, 256>>>(
        x, h0, qA, pdA, qB, pdB, Wts, Wst + 128, Wst, Wts + 128);

    // pass 1: inter L0, relu; fused dots for pass 2 (intra L1) -> set A
    k_gather<false, true, true><<<ng, 256>>>(
        h0, h1, qB, pdB, qA, pdA, Wss + 256, Wss + 384, Wtt + 256, Wtt + 384);

    // pass 2: intra L1, relu; fused dots for pass 3 (inter L1) -> set B
    k_gather<true, true, true><<<ng, 256>>>(
        h1, h0, qA, pdA, qB, pdB, Wts + 256, Wst + 384, Wst + 256, Wts + 384);

    // pass 3: inter L1, no relu, write straight to d_out
    k_gather<false, false, false><<<ng, 256>>>(
        h0, out, qB, pdB, nullptr, nullptr, nullptr, nullptr, nullptr, nullptr);
}